// round 2
// baseline (speedup 1.0000x reference)
#include <cuda_runtime.h>

// Loss: per joint (3 floats): d = p - l; s2 = d2^2;
// term = (p2 > 0.5) ? (d0^2+d1^2+d2^2)/3 : s2 ; answer = sum(term)/B.
// Layout: [B, 54] fp32 contiguous -> B*18 joints of 3 floats.
// Process 8 joints (2 groups of 3 float4) per thread-iteration with
// streaming (__ldcs) loads, 12 LDG.128 front-batched per body for MLP.

__device__ __forceinline__ float joint_term(float p0, float p1, float p2,
                                            float l0, float l1, float l2) {
    float d0 = p0 - l0, d1 = p1 - l1, d2 = p2 - l2;
    float s2 = d2 * d2;
    float full = (d0 * d0 + d1 * d1 + s2) * (1.0f / 3.0f);
    return (p2 > 0.5f) ? full : s2;
}

__device__ __forceinline__ float group4(float4 a, float4 b, float4 c,
                                        float4 x, float4 y, float4 z) {
    float acc;
    acc  = joint_term(a.x, a.y, a.z, x.x, x.y, x.z);
    acc += joint_term(a.w, b.x, b.y, x.w, y.x, y.y);
    acc += joint_term(b.z, b.w, c.x, y.z, y.w, z.x);
    acc += joint_term(c.y, c.z, c.w, z.y, z.z, z.w);
    return acc;
}

__global__ void init_out_kernel(float* out) {
    if (threadIdx.x == 0) out[0] = 0.0f;
}

__global__ void __launch_bounds__(256)
loss_kernel(const float4* __restrict__ P, const float4* __restrict__ L,
            float* __restrict__ out, int npairs, float inv_b) {
    float acc = 0.0f;
    int stride = gridDim.x * blockDim.x;
    for (int g = blockIdx.x * blockDim.x + threadIdx.x; g < npairs; g += stride) {
        int base = 6 * g;
        // front-batch all 12 LDG.128 (streaming, evict-first)
        float4 p0 = __ldcs(P + base + 0);
        float4 p1 = __ldcs(P + base + 1);
        float4 p2 = __ldcs(P + base + 2);
        float4 p3 = __ldcs(P + base + 3);
        float4 p4 = __ldcs(P + base + 4);
        float4 p5 = __ldcs(P + base + 5);
        float4 l0 = __ldcs(L + base + 0);
        float4 l1 = __ldcs(L + base + 1);
        float4 l2 = __ldcs(L + base + 2);
        float4 l3 = __ldcs(L + base + 3);
        float4 l4 = __ldcs(L + base + 4);
        float4 l5 = __ldcs(L + base + 5);
        acc += group4(p0, p1, p2, l0, l1, l2);
        acc += group4(p3, p4, p5, l3, l4, l5);
    }

    // warp reduce
    #pragma unroll
    for (int off = 16; off; off >>= 1)
        acc += __shfl_down_sync(0xFFFFFFFFu, acc, off);

    __shared__ float ws[8];
    int lane = threadIdx.x & 31;
    int wid  = threadIdx.x >> 5;
    if (lane == 0) ws[wid] = acc;
    __syncthreads();
    if (wid == 0) {
        acc = (lane < 8) ? ws[lane] : 0.0f;
        #pragma unroll
        for (int off = 4; off; off >>= 1)
            acc += __shfl_down_sync(0xFFFFFFFFu, acc, off);
        if (lane == 0) atomicAdd(out, acc * inv_b);
    }
}

extern "C" void kernel_launch(void* const* d_in, const int* in_sizes, int n_in,
                              void* d_out, int out_size) {
    const float4* P = (const float4*)d_in[0];
    const float4* L = (const float4*)d_in[1];
    float* out = (float*)d_out;

    long long total_floats = (long long)in_sizes[0];     // B * 54
    long long B = total_floats / 54;
    int npairs = (int)(total_floats / 24);               // 8-joint pairs

    init_out_kernel<<<1, 32>>>(out);

    const int threads = 256;
    const int blocks = 148 * 16;
    loss_kernel<<<blocks, threads>>>(P, L, out, npairs, 1.0f / (float)B);
}